// round 2
// baseline (speedup 1.0000x reference)
#include <cuda_runtime.h>
#include <math.h>

#define B_    2
#define NSEQ  4096
#define H_    4
#define DK    256
#define DV    512
#define DM    1024
#define VD    2048
#define NC    64

// ---------------- static scratch (allocation-free rule) ----------------
__device__ float g_q1[(size_t)B_ * NSEQ * DM];   // raw q proj (B*N, 1024)
__device__ float g_k1[(size_t)B_ * NSEQ * DM];   // raw k proj
__device__ float g_q [(size_t)B_ * NSEQ * DM];   // (B,H,N,dk) after rope+scale
__device__ float g_k [(size_t)B_ * NSEQ * DM];   // (B,H,N,dk) after rope
__device__ float g_v [(size_t)B_ * NSEQ * VD];   // (B,H,N,dv)
__device__ float g_g [(size_t)B_ * NSEQ * VD];   // silu(x@Wg), (B*N, 2048); overwritten by norm*gate
__device__ float g_o [(size_t)B_ * NSEQ * VD];   // retention out (B,N,H,dv)
__device__ float g_U [(size_t)B_ * H_ * NC * DK * DV];  // per-chunk K^T V (256MB)
__device__ float g_S [(size_t)B_ * H_ * NC * DK * DV];  // per-chunk prefix states (256MB)
__device__ float g_cos[(size_t)NSEQ * 128];
__device__ float g_sin[(size_t)NSEQ * 128];

// ---------------- generic fp32 SGEMM: C = A(MxK) @ W(KxN) ----------------
// EPI: 0 = plain row-major, 1 = silu row-major, 2 = write to (B,H,N,dv) transposed layout
template <int EPI>
__global__ __launch_bounds__(256, 2)
void sgemm(const float* __restrict__ A, const float* __restrict__ W,
           float* __restrict__ C, int M, int Ncols, int K)
{
    __shared__ float As[16][132];   // As[k][m], padded
    __shared__ float Bs[16][128];   // Bs[k][n]

    const int tid = threadIdx.x;
    const int bm = blockIdx.y * 128;
    const int bn = blockIdx.x * 128;
    const int ty = tid >> 4, tx = tid & 15;

    // A tile loads: 128 rows x 16 cols
    const int arow = tid >> 2;          // 0..63 (and +64)
    const int acol = (tid & 3) * 4;     // 0,4,8,12
    // W tile loads: 16 rows x 128 cols
    const int wrow = tid >> 5;          // 0..7 (and +8)
    const int wcol = (tid & 31) * 4;

    const float* Ap = A + (size_t)bm * K;
    const float* Wp = W + bn;

    float acc[8][8];
    #pragma unroll
    for (int m = 0; m < 8; m++)
        #pragma unroll
        for (int n = 0; n < 8; n++) acc[m][n] = 0.0f;

    for (int k0 = 0; k0 < K; k0 += 16) {
        float4 a0 = *(const float4*)(Ap + (size_t)arow * K + k0 + acol);
        float4 a1 = *(const float4*)(Ap + (size_t)(arow + 64) * K + k0 + acol);
        As[acol + 0][arow] = a0.x; As[acol + 1][arow] = a0.y;
        As[acol + 2][arow] = a0.z; As[acol + 3][arow] = a0.w;
        As[acol + 0][arow + 64] = a1.x; As[acol + 1][arow + 64] = a1.y;
        As[acol + 2][arow + 64] = a1.z; As[acol + 3][arow + 64] = a1.w;

        float4 w0 = *(const float4*)(Wp + (size_t)(k0 + wrow) * Ncols + wcol);
        float4 w1 = *(const float4*)(Wp + (size_t)(k0 + wrow + 8) * Ncols + wcol);
        *(float4*)&Bs[wrow][wcol] = w0;
        *(float4*)&Bs[wrow + 8][wcol] = w1;
        __syncthreads();

        #pragma unroll
        for (int kk = 0; kk < 16; kk++) {
            float4 av0 = *(const float4*)&As[kk][ty * 8];
            float4 av1 = *(const float4*)&As[kk][ty * 8 + 4];
            float4 bv0 = *(const float4*)&Bs[kk][tx * 8];
            float4 bv1 = *(const float4*)&Bs[kk][tx * 8 + 4];
            float ar[8] = {av0.x, av0.y, av0.z, av0.w, av1.x, av1.y, av1.z, av1.w};
            float br[8] = {bv0.x, bv0.y, bv0.z, bv0.w, bv1.x, bv1.y, bv1.z, bv1.w};
            #pragma unroll
            for (int m = 0; m < 8; m++)
                #pragma unroll
                for (int n = 0; n < 8; n++) acc[m][n] += ar[m] * br[n];
        }
        __syncthreads();
    }

    #pragma unroll
    for (int m = 0; m < 8; m++) {
        const int row = bm + ty * 8 + m;
        #pragma unroll
        for (int n4 = 0; n4 < 2; n4++) {
            float4 o;
            o.x = acc[m][n4 * 4 + 0];
            o.y = acc[m][n4 * 4 + 1];
            o.z = acc[m][n4 * 4 + 2];
            o.w = acc[m][n4 * 4 + 3];
            const int col = bn + tx * 8 + n4 * 4;
            if (EPI == 1) {
                o.x = o.x / (1.0f + expf(-o.x));
                o.y = o.y / (1.0f + expf(-o.y));
                o.z = o.z / (1.0f + expf(-o.z));
                o.w = o.w / (1.0f + expf(-o.w));
            }
            if (EPI == 2) {
                const int bb = row >> 12, nn = row & 4095;
                const int hh = col >> 9,  ee = col & 511;
                *(float4*)(C + (((size_t)(bb * H_ + hh)) * NSEQ + nn) * DV + ee) = o;
            } else {
                *(float4*)(C + (size_t)row * Ncols + col) = o;
            }
        }
    }
}

// ---------------- rotary table: accurate range reduction in double ----------------
__global__ void rope_table(float* __restrict__ cosT, float* __restrict__ sinT)
{
    const int t = blockIdx.x;    // 0..4095
    const int i = threadIdx.x;   // 0..127
    const double m = (double)i * (1.0 / 128.0);
    const double invf = exp(-m * 9.210340371976184);   // 10000^(-i/128)
    const float pf = (float)t * (float)invf;           // match f32 rounding of phases
    const double ph = (double)pf;
    const double kq = rint(ph * 0.15915494309189535);  // /(2*pi)
    const float rf = (float)(ph - kq * 6.283185307179586);
    cosT[t * 128 + i] = cosf(rf);
    sinT[t * 128 + i] = sinf(rf);
}

// ---------------- rotary + transpose to (B,H,N,dk), q scaled ----------------
__global__ void rope_apply(const float* __restrict__ Q1, const float* __restrict__ K1,
                           float* __restrict__ Qo, float* __restrict__ Ko,
                           const float* __restrict__ cosT, const float* __restrict__ sinT)
{
    const int idx = blockIdx.x * blockDim.x + threadIdx.x;  // < 2*4096*4*128
    const int i  = idx & 127;
    const int hh = (idx >> 7) & 3;
    const int n  = (idx >> 9) & 4095;
    const int b  = idx >> 21;
    const float cv = cosT[n * 128 + i];
    const float sv = sinT[n * 128 + i];
    const size_t src = ((size_t)(b * NSEQ + n)) * DM + hh * DK + i;
    const size_t dst = (((size_t)(b * H_ + hh)) * NSEQ + n) * DK + i;

    const float qa = Q1[src], qb = Q1[src + 128];
    Qo[dst]       = (qa * cv - qb * sv) * 0.0625f;   // * HEAD_QK^-0.5
    Qo[dst + 128] = (qb * cv + qa * sv) * 0.0625f;
    const float ka = K1[src], kb = K1[src + 128];
    Ko[dst]       = ka * cv - kb * sv;
    Ko[dst + 128] = kb * cv + ka * sv;
}

// ---------------- phase A: U_c = (k ⊙ gamma^(63-j))^T @ v, per chunk ----------------
__global__ __launch_bounds__(256, 2)
void chunk_kv(const float* __restrict__ K, const float* __restrict__ V,
              float* __restrict__ U)
{
    __shared__ float Ks[16][132];
    __shared__ float Vs[16][132];

    const int tid = threadIdx.x;
    const int z = blockIdx.z;          // bh*64 + c
    const int bh = z >> 6, c = z & 63;
    const int h = bh & 3;
    const float gamma = 1.0f - exp2f(-(float)(5 + h));
    const int d0 = blockIdx.y * 128;
    const int e0 = blockIdx.x * 128;

    const float* kptr = K + ((size_t)bh * NSEQ + c * 64) * DK;
    const float* vptr = V + ((size_t)bh * NSEQ + c * 64) * DV;
    float* uptr = U + (size_t)z * DK * DV;

    const int ty = tid >> 4, tx = tid & 15;
    const int jr = tid >> 5, jc = (tid & 31) * 4;

    float acc[8][8];
    #pragma unroll
    for (int m = 0; m < 8; m++)
        #pragma unroll
        for (int n = 0; n < 8; n++) acc[m][n] = 0.0f;

    for (int j0 = 0; j0 < 64; j0 += 16) {
        const float s0 = powf(gamma, (float)(63 - (j0 + jr)));
        const float s1 = powf(gamma, (float)(63 - (j0 + jr + 8)));
        float4 kv0 = *(const float4*)(kptr + (size_t)(j0 + jr) * DK + d0 + jc);
        float4 kv1 = *(const float4*)(kptr + (size_t)(j0 + jr + 8) * DK + d0 + jc);
        kv0.x *= s0; kv0.y *= s0; kv0.z *= s0; kv0.w *= s0;
        kv1.x *= s1; kv1.y *= s1; kv1.z *= s1; kv1.w *= s1;
        *(float4*)&Ks[jr][jc] = kv0;
        *(float4*)&Ks[jr + 8][jc] = kv1;
        *(float4*)&Vs[jr][jc]     = *(const float4*)(vptr + (size_t)(j0 + jr) * DV + e0 + jc);
        *(float4*)&Vs[jr + 8][jc] = *(const float4*)(vptr + (size_t)(j0 + jr + 8) * DV + e0 + jc);
        __syncthreads();

        #pragma unroll
        for (int kk = 0; kk < 16; kk++) {
            float4 a0 = *(const float4*)&Ks[kk][ty * 8];
            float4 a1 = *(const float4*)&Ks[kk][ty * 8 + 4];
            float4 b0 = *(const float4*)&Vs[kk][tx * 8];
            float4 b1 = *(const float4*)&Vs[kk][tx * 8 + 4];
            float ar[8] = {a0.x, a0.y, a0.z, a0.w, a1.x, a1.y, a1.z, a1.w};
            float br[8] = {b0.x, b0.y, b0.z, b0.w, b1.x, b1.y, b1.z, b1.w};
            #pragma unroll
            for (int m = 0; m < 8; m++)
                #pragma unroll
                for (int n = 0; n < 8; n++) acc[m][n] += ar[m] * br[n];
        }
        __syncthreads();
    }

    #pragma unroll
    for (int m = 0; m < 8; m++) {
        const size_t rowoff = (size_t)(d0 + ty * 8 + m) * DV + e0 + tx * 8;
        float4 o0, o1;
        o0.x = acc[m][0]; o0.y = acc[m][1]; o0.z = acc[m][2]; o0.w = acc[m][3];
        o1.x = acc[m][4]; o1.y = acc[m][5]; o1.z = acc[m][6]; o1.w = acc[m][7];
        *(float4*)(uptr + rowoff) = o0;
        *(float4*)(uptr + rowoff + 4) = o1;
    }
}

// ---------------- phase B: decay scan over chunks (element-parallel) ----------------
__global__ void scan_state(const float* __restrict__ U, float* __restrict__ S)
{
    const int idx = blockIdx.x * blockDim.x + threadIdx.x;  // < 8*131072
    const int bh = idx >> 17;
    const int de = idx & 131071;
    const int h = bh & 3;
    const float gamma = 1.0f - exp2f(-(float)(5 + h));
    const float gC = powf(gamma, 64.0f);
    const size_t base = ((size_t)bh * 64) * 131072 + de;
    float s = 0.0f;
    for (int c = 0; c < 64; c++) {
        const size_t off = base + (size_t)c * 131072;
        S[off] = s;                 // state used BY chunk c
        s = gC * s + U[off];
    }
}

// ---------------- phase C: o = mask(q k^T) v + (q ⊙ gamma^(i+1)) S ----------------
__global__ __launch_bounds__(256, 2)
void retention_out(const float* __restrict__ Q, const float* __restrict__ K,
                   const float* __restrict__ V, const float* __restrict__ S,
                   float* __restrict__ O)
{
    __shared__ float attnS[64][65];
    __shared__ union {
        struct { float Qt[32][68]; float Kt[32][68]; } s1;  // stage 1 transposed chunks
        struct { float Buf[16][132]; float Qd[16][68]; } s2; // stage 2 streaming
    } sh;
    __shared__ float gpow[66];

    const int tid = threadIdx.x;
    const int z = blockIdx.y;          // bh*64 + c
    const int bh = z >> 6, c = z & 63;
    const int h = bh & 3, b = bh >> 2;
    const int e0 = blockIdx.x * 128;
    const float gamma = 1.0f - exp2f(-(float)(5 + h));
    if (tid < 66) gpow[tid] = powf(gamma, (float)tid);

    const float* qptr = Q + ((size_t)bh * NSEQ + c * 64) * DK;
    const float* kptr = K + ((size_t)bh * NSEQ + c * 64) * DK;
    const float* vptr = V + ((size_t)bh * NSEQ + c * 64) * DV;
    const float* sptr = S + (size_t)z * DK * DV;

    // ---- stage 1: attn (64x64) with decay mask ----
    const int aty = tid >> 4, atx = tid & 15;
    float at[4][4] = {{0}};
    const int li = tid >> 3, lc = (tid & 7) * 4;

    for (int d0 = 0; d0 < DK; d0 += 32) {
        float4 q0 = *(const float4*)(qptr + (size_t)li * DK + d0 + lc);
        float4 q1 = *(const float4*)(qptr + (size_t)(li + 32) * DK + d0 + lc);
        float4 k0 = *(const float4*)(kptr + (size_t)li * DK + d0 + lc);
        float4 k1 = *(const float4*)(kptr + (size_t)(li + 32) * DK + d0 + lc);
        sh.s1.Qt[lc + 0][li] = q0.x; sh.s1.Qt[lc + 1][li] = q0.y;
        sh.s1.Qt[lc + 2][li] = q0.z; sh.s1.Qt[lc + 3][li] = q0.w;
        sh.s1.Qt[lc + 0][li + 32] = q1.x; sh.s1.Qt[lc + 1][li + 32] = q1.y;
        sh.s1.Qt[lc + 2][li + 32] = q1.z; sh.s1.Qt[lc + 3][li + 32] = q1.w;
        sh.s1.Kt[lc + 0][li] = k0.x; sh.s1.Kt[lc + 1][li] = k0.y;
        sh.s1.Kt[lc + 2][li] = k0.z; sh.s1.Kt[lc + 3][li] = k0.w;
        sh.s1.Kt[lc + 0][li + 32] = k1.x; sh.s1.Kt[lc + 1][li + 32] = k1.y;
        sh.s1.Kt[lc + 2][li + 32] = k1.z; sh.s1.Kt[lc + 3][li + 32] = k1.w;
        __syncthreads();

        #pragma unroll
        for (int dd = 0; dd < 32; dd++) {
            float4 qa = *(const float4*)&sh.s1.Qt[dd][aty * 4];
            float4 kb = *(const float4*)&sh.s1.Kt[dd][atx * 4];
            float ar[4] = {qa.x, qa.y, qa.z, qa.w};
            float br[4] = {kb.x, kb.y, kb.z, kb.w};
            #pragma unroll
            for (int r = 0; r < 4; r++)
                #pragma unroll
                for (int cc = 0; cc < 4; cc++) at[r][cc] += ar[r] * br[cc];
        }
        __syncthreads();
    }

    #pragma unroll
    for (int r = 0; r < 4; r++) {
        const int i = aty * 4 + r;
        #pragma unroll
        for (int cc = 0; cc < 4; cc++) {
            const int j = atx * 4 + cc;
            attnS[i][j] = (i >= j) ? at[r][cc] * gpow[i - j] : 0.0f;
        }
    }
    __syncthreads();

    // ---- stage 2 ----
    const int ry = tid >> 4, rx = tid & 15;
    const int i0 = ry * 4;
    const int ecol = rx * 8;
    const int jr = tid >> 5, jc = (tid & 31) * 4;

    float acc[4][8] = {{0}};
    float acci[4][8] = {{0}};

    // intra: attn @ V (K = 64)
    for (int j0 = 0; j0 < 64; j0 += 16) {
        *(float4*)&sh.s2.Buf[jr][jc]     = *(const float4*)(vptr + (size_t)(j0 + jr) * DV + e0 + jc);
        *(float4*)&sh.s2.Buf[jr + 8][jc] = *(const float4*)(vptr + (size_t)(j0 + jr + 8) * DV + e0 + jc);
        __syncthreads();
        #pragma unroll
        for (int jj = 0; jj < 16; jj++) {
            float4 b0 = *(const float4*)&sh.s2.Buf[jj][ecol];
            float4 b1 = *(const float4*)&sh.s2.Buf[jj][ecol + 4];
            float br[8] = {b0.x, b0.y, b0.z, b0.w, b1.x, b1.y, b1.z, b1.w};
            float ar[4];
            #pragma unroll
            for (int r = 0; r < 4; r++) ar[r] = attnS[i0 + r][j0 + jj];
            #pragma unroll
            for (int r = 0; r < 4; r++)
                #pragma unroll
                for (int n = 0; n < 8; n++) acc[r][n] += ar[r] * br[n];
        }
        __syncthreads();
    }

    // inter: q @ S (K = 256)
    const int li2 = tid >> 2, lc2 = (tid & 3) * 4;
    for (int d0 = 0; d0 < DK; d0 += 16) {
        *(float4*)&sh.s2.Buf[jr][jc]     = *(const float4*)(sptr + (size_t)(d0 + jr) * DV + e0 + jc);
        *(float4*)&sh.s2.Buf[jr + 8][jc] = *(const float4*)(sptr + (size_t)(d0 + jr + 8) * DV + e0 + jc);
        float4 qv = *(const float4*)(qptr + (size_t)li2 * DK + d0 + lc2);
        sh.s2.Qd[lc2 + 0][li2] = qv.x; sh.s2.Qd[lc2 + 1][li2] = qv.y;
        sh.s2.Qd[lc2 + 2][li2] = qv.z; sh.s2.Qd[lc2 + 3][li2] = qv.w;
        __syncthreads();
        #pragma unroll
        for (int dd = 0; dd < 16; dd++) {
            float4 b0 = *(const float4*)&sh.s2.Buf[dd][ecol];
            float4 b1 = *(const float4*)&sh.s2.Buf[dd][ecol + 4];
            float4 qa = *(const float4*)&sh.s2.Qd[dd][i0];
            float br[8] = {b0.x, b0.y, b0.z, b0.w, b1.x, b1.y, b1.z, b1.w};
            float ar[4] = {qa.x, qa.y, qa.z, qa.w};
            #pragma unroll
            for (int r = 0; r < 4; r++)
                #pragma unroll
                for (int n = 0; n < 8; n++) acci[r][n] += ar[r] * br[n];
        }
        __syncthreads();
    }

    // o[i][e] = intra + gamma^(i+1) * inter, write to (B,N,H,dv)
    #pragma unroll
    for (int r = 0; r < 4; r++) {
        const int i = i0 + r;
        const float cq = gpow[i + 1];
        const size_t dst = (((size_t)(b * NSEQ + c * 64 + i)) * H_ + h) * DV + e0 + ecol;
        float4 o0, o1;
        o0.x = acc[r][0] + cq * acci[r][0];
        o0.y = acc[r][1] + cq * acci[r][1];
        o0.z = acc[r][2] + cq * acci[r][2];
        o0.w = acc[r][3] + cq * acci[r][3];
        o1.x = acc[r][4] + cq * acci[r][4];
        o1.y = acc[r][5] + cq * acci[r][5];
        o1.z = acc[r][6] + cq * acci[r][6];
        o1.w = acc[r][7] + cq * acci[r][7];
        *(float4*)(O + dst) = o0;
        *(float4*)(O + dst + 4) = o1;
    }
}

// ---------------- rmsnorm (per head) * silu-gate, in place into G ----------------
__global__ void norm_gate(const float* __restrict__ O, float* __restrict__ G,
                          const float* __restrict__ w)
{
    __shared__ float red[4];
    const int row = blockIdx.x;          // (b*4096+n)*4 + h, 0..32767
    const int tid = threadIdx.x;         // 128 threads, 4 elems each
    const size_t base = (size_t)row * DV;

    float4 x = *(const float4*)(O + base + tid * 4);
    float ss = x.x * x.x + x.y * x.y + x.z * x.z + x.w * x.w;
    #pragma unroll
    for (int off = 16; off; off >>= 1) ss += __shfl_xor_sync(0xffffffff, ss, off);
    if ((tid & 31) == 0) red[tid >> 5] = ss;
    __syncthreads();
    const float tot = red[0] + red[1] + red[2] + red[3];
    const float inv = rsqrtf(tot * (1.0f / (float)DV) + 1e-5f);

    float4 wv = *(const float4*)(w + tid * 4);
    float4 gv = *(const float4*)(G + base + tid * 4);
    float4 o;
    o.x = x.x * inv * wv.x * gv.x;
    o.y = x.y * inv * wv.y * gv.y;
    o.z = x.z * inv * wv.z * gv.z;
    o.w = x.w * inv * wv.w * gv.w;
    *(float4*)(G + base + tid * 4) = o;
}

// ---------------- launch ----------------
extern "C" void kernel_launch(void* const* d_in, const int* in_sizes, int n_in,
                              void* d_out, int out_size)
{
    const float* x  = (const float*)d_in[0];
    const float* Wq = (const float*)d_in[1];
    const float* Wk = (const float*)d_in[2];
    const float* Wv = (const float*)d_in[3];
    const float* Wg = (const float*)d_in[4];
    const float* Wo = (const float*)d_in[5];
    const float* gw = (const float*)d_in[6];
    float* out = (float*)d_out;

    float *q1, *k1, *q, *k, *v, *g, *o, *U, *S, *ct, *st;
    cudaGetSymbolAddress((void**)&q1, g_q1);
    cudaGetSymbolAddress((void**)&k1, g_k1);
    cudaGetSymbolAddress((void**)&q,  g_q);
    cudaGetSymbolAddress((void**)&k,  g_k);
    cudaGetSymbolAddress((void**)&v,  g_v);
    cudaGetSymbolAddress((void**)&g,  g_g);
    cudaGetSymbolAddress((void**)&o,  g_o);
    cudaGetSymbolAddress((void**)&U,  g_U);
    cudaGetSymbolAddress((void**)&S,  g_S);
    cudaGetSymbolAddress((void**)&ct, g_cos);
    cudaGetSymbolAddress((void**)&st, g_sin);

    const int M = B_ * NSEQ;  // 8192
    dim3 blk(256);

    // projections
    sgemm<0><<<dim3(DM / 128, M / 128), blk>>>(x, Wq, q1, M, DM, DM);
    sgemm<0><<<dim3(DM / 128, M / 128), blk>>>(x, Wk, k1, M, DM, DM);
    sgemm<2><<<dim3(VD / 128, M / 128), blk>>>(x, Wv, v, M, VD, DM);
    sgemm<1><<<dim3(VD / 128, M / 128), blk>>>(x, Wg, g, M, VD, DM);

    // rotary
    rope_table<<<NSEQ, 128>>>(ct, st);
    rope_apply<<<(B_ * NSEQ * H_ * 128) / 256, 256>>>(q1, k1, q, k, ct, st);

    // retention (parallelized chunk scan)
    chunk_kv<<<dim3(DV / 128, DK / 128, B_ * H_ * NC), blk>>>(k, v, U);
    scan_state<<<(B_ * H_ * DK * DV) / 256, 256>>>(U, S);
    retention_out<<<dim3(DV / 128, B_ * H_ * NC), blk>>>(q, k, v, S, o);

    // rmsnorm + gate, then output projection
    norm_gate<<<B_ * NSEQ * H_, 128>>>(o, g, gw);
    sgemm<0><<<dim3(DM / 128, M / 128), blk>>>(g, Wo, out, M, DM, VD);
}